// round 16
// baseline (speedup 1.0000x reference)
#include <cuda_runtime.h>
#include <math.h>

// Problem constants
#define EMBED 1024
#define NHEADS 16
#define HDIM 64
#define BATCH 2
#define SEQ 2048
#define MROWS (BATCH * SEQ)        // 4096
#define QKV_COLS (3 * EMBED)       // 3072
#define ATT_SCALE 0.125f           // 64^-0.5

// Scratch (allocation-free rule: __device__ globals)
__device__ float g_qkv[3 * BATCH * NHEADS * SEQ * HDIM];
__device__ float g_attn[BATCH * SEQ * EMBED];

// ---------------------------------------------------------------------------
// Packed f32x2 helpers (proven-passing path)
// ---------------------------------------------------------------------------
#define F2FMA(d, a, b) \
    asm("fma.rn.f32x2 %0, %1, %2, %0;" : "+l"(d) : "l"(a), "l"(b))
#define F2MUL(d, a, b) \
    asm("mul.rn.f32x2 %0, %1, %2;" : "=l"(d) : "l"(a), "l"(b))
#define F2MULI(d, b) \
    asm("mul.rn.f32x2 %0, %0, %1;" : "+l"(d) : "l"(b))
#define F2ADDI(d, b) \
    asm("add.rn.f32x2 %0, %0, %1;" : "+l"(d) : "l"(b))
#define PACK2(d, lo, hi) \
    asm("mov.b64 %0, {%1, %2};" : "=l"(d) : "f"(lo), "f"(hi))
#define UNPACK2(lo, hi, v) \
    asm("mov.b64 {%0, %1}, %2;" : "=f"(lo), "=f"(hi) : "l"(v))

// ---------------------------------------------------------------------------
// GEMM 1: qkv = x @ w_qkv + b_qkv (f32x2, PROVEN PASSING — unchanged from R12)
// ---------------------------------------------------------------------------
__global__ __launch_bounds__(256, 2)
void qkv_gemm(const float* __restrict__ A,
              const float* __restrict__ W,
              const float* __restrict__ bias)
{
    __shared__ float As[2][16][132];
    __shared__ float Bs[2][16][128];

    const int K = EMBED;
    const int NC = QKV_COLS;
    const int tid = threadIdx.x;
    const int m0 = blockIdx.y * 128;
    const int n0 = blockIdx.x * 128;
    const int tx = tid & 15;
    const int ty = tid >> 4;

    const int arow0 = tid >> 2, ac4 = tid & 3;
    const int arow1 = arow0 + 64;
    const int brow0 = tid >> 5, bc4 = tid & 31;
    const int brow1 = brow0 + 8;

    unsigned long long acc2[8][4];
#pragma unroll
    for (int i = 0; i < 8; i++)
#pragma unroll
        for (int j = 0; j < 4; j++) acc2[i][j] = 0ULL;

    float4 ra0, ra1, rb0, rb1;
    ra0 = *(const float4*)&A[(size_t)(m0 + arow0) * K + ac4 * 4];
    ra1 = *(const float4*)&A[(size_t)(m0 + arow1) * K + ac4 * 4];
    rb0 = *(const float4*)&W[(size_t)brow0 * NC + n0 + bc4 * 4];
    rb1 = *(const float4*)&W[(size_t)brow1 * NC + n0 + bc4 * 4];

    for (int i = 0; i < K / 16; i++) {
        const int s = i & 1;

        As[s][ac4 * 4 + 0][arow0] = ra0.x;
        As[s][ac4 * 4 + 1][arow0] = ra0.y;
        As[s][ac4 * 4 + 2][arow0] = ra0.z;
        As[s][ac4 * 4 + 3][arow0] = ra0.w;
        As[s][ac4 * 4 + 0][arow1] = ra1.x;
        As[s][ac4 * 4 + 1][arow1] = ra1.y;
        As[s][ac4 * 4 + 2][arow1] = ra1.z;
        As[s][ac4 * 4 + 3][arow1] = ra1.w;
        *(float4*)&Bs[s][brow0][bc4 * 4] = rb0;
        *(float4*)&Bs[s][brow1][bc4 * 4] = rb1;

        if (i + 1 < K / 16) {
            int k0 = (i + 1) * 16;
            ra0 = *(const float4*)&A[(size_t)(m0 + arow0) * K + k0 + ac4 * 4];
            ra1 = *(const float4*)&A[(size_t)(m0 + arow1) * K + k0 + ac4 * 4];
            rb0 = *(const float4*)&W[(size_t)(k0 + brow0) * NC + n0 + bc4 * 4];
            rb1 = *(const float4*)&W[(size_t)(k0 + brow1) * NC + n0 + bc4 * 4];
        }

        __syncthreads();

#pragma unroll
        for (int kk = 0; kk < 16; kk++) {
            float a[8];
            *(float4*)&a[0] = *(const float4*)&As[s][kk][ty * 8];
            *(float4*)&a[4] = *(const float4*)&As[s][kk][ty * 8 + 4];
            ulonglong2 b01 = *(const ulonglong2*)&Bs[s][kk][tx * 8];
            ulonglong2 b23 = *(const ulonglong2*)&Bs[s][kk][tx * 8 + 4];
#pragma unroll
            for (int ii = 0; ii < 8; ii++) {
                unsigned long long a2;
                PACK2(a2, a[ii], a[ii]);
                F2FMA(acc2[ii][0], a2, b01.x);
                F2FMA(acc2[ii][1], a2, b01.y);
                F2FMA(acc2[ii][2], a2, b23.x);
                F2FMA(acc2[ii][3], a2, b23.y);
            }
        }
    }

    {
        int jc0 = n0 + tx * 8;
        int sI = jc0 >> 10;
        int rem = jc0 & 1023;
        int h = rem >> 6;
        int d = rem & 63;
        float b0 = bias[jc0 + 0], b1 = bias[jc0 + 1], b2 = bias[jc0 + 2], b3 = bias[jc0 + 3];
        float b4 = bias[jc0 + 4], b5 = bias[jc0 + 5], b6 = bias[jc0 + 6], b7 = bias[jc0 + 7];
#pragma unroll
        for (int i = 0; i < 8; i++) {
            int m = m0 + ty * 8 + i;
            int b = m >> 11;
            int n = m & 2047;
            float c0, c1, c2, c3, c4, c5, c6, c7;
            UNPACK2(c0, c1, acc2[i][0]);
            UNPACK2(c2, c3, acc2[i][1]);
            UNPACK2(c4, c5, acc2[i][2]);
            UNPACK2(c6, c7, acc2[i][3]);
            float* dst = &g_qkv[(((size_t)((sI * BATCH + b) * NHEADS + h)) * SEQ + n) * HDIM + d];
            float4 v0, v1;
            v0.x = c0 + b0; v0.y = c1 + b1; v0.z = c2 + b2; v0.w = c3 + b3;
            v1.x = c4 + b4; v1.y = c5 + b5; v1.z = c6 + b6; v1.w = c7 + b7;
            *(float4*)dst = v0;
            *(float4*)(dst + 4) = v1;
        }
    }
}

// ---------------------------------------------------------------------------
// Flash attention v3: HALF-ROW per thread for occupancy.
// 128 threads = 64 query rows; lane pairs share a row (shfl combine).
// Scores staged in smem (warp-private) to keep regs ~100 -> 5 CTAs/SM.
// Single-buffered K/V tiles of 32 keys.
// ---------------------------------------------------------------------------
#define BN 32

__global__ __launch_bounds__(128)
void attn_half()
{
    __shared__ float Ks[BN][HDIM];
    __shared__ float Vss[BN][HDIM];
    __shared__ float svs[BN][64];

    const int tid = threadIdx.x;
    const int row = tid >> 1;             // local row 0..63
    const int half = tid & 1;             // dim half
    const int bh = blockIdx.y;            // 0..31
    const int r = blockIdx.x * 64 + row;  // global query row

    const float* Qp = g_qkv + ((size_t)bh * SEQ + r) * HDIM + half * 32;
    const float* Kb = g_qkv + ((size_t)(32 + bh) * SEQ) * HDIM;
    const float* Vb = g_qkv + ((size_t)(64 + bh) * SEQ) * HDIM;

    // q: own 32 dims = 16 u64, pre-scaled
    unsigned long long q2[16];
    {
        unsigned long long sc2;
        PACK2(sc2, ATT_SCALE, ATT_SCALE);
        const ulonglong2* Qp2 = (const ulonglong2*)Qp;
#pragma unroll
        for (int i = 0; i < 8; i++) {
            ulonglong2 tq = Qp2[i];
            F2MUL(q2[2 * i],     tq.x, sc2);
            F2MUL(q2[2 * i + 1], tq.y, sc2);
        }
    }

    unsigned long long o2[16];
#pragma unroll
    for (int i = 0; i < 16; i++) o2[i] = 0ULL;
    float mi = -INFINITY, li = 0.f;

    for (int t = 0; t < SEQ / BN; t++) {
        const int kb = t * BN;

        __syncthreads();   // prior tile's smem reads complete
        // load K,V tile: 32x64 each; 4 float4 per thread per matrix
#pragma unroll
        for (int i = 0; i < 4; i++) {
            int idx = tid + i * 128;
            int kr = idx >> 4, c4 = idx & 15;
            *(float4*)&Ks[kr][c4 * 4]  = *(const float4*)&Kb[(size_t)(kb + kr) * HDIM + c4 * 4];
            *(float4*)&Vss[kr][c4 * 4] = *(const float4*)&Vb[(size_t)(kb + kr) * HDIM + c4 * 4];
        }
        __syncthreads();

        // ---- S pass: s_j = q . K_j (half-dot + shuffle combine) ----
        float tmax = mi;
#pragma unroll 8
        for (int j = 0; j < BN; j++) {
            unsigned long long c0 = 0ULL, c1 = 0ULL, c2 = 0ULL, c3 = 0ULL;
            const ulonglong2* kp = (const ulonglong2*)&Ks[j][half * 32];
#pragma unroll
            for (int dd = 0; dd < 4; dd++) {
                ulonglong2 k0 = kp[2 * dd];
                ulonglong2 k1 = kp[2 * dd + 1];
                F2FMA(c0, q2[4 * dd + 0], k0.x);
                F2FMA(c1, q2[4 * dd + 1], k0.y);
                F2FMA(c2, q2[4 * dd + 2], k1.x);
                F2FMA(c3, q2[4 * dd + 3], k1.y);
            }
            F2ADDI(c0, c2);
            F2ADDI(c1, c3);
            F2ADDI(c0, c1);
            float lo, hi;
            UNPACK2(lo, hi, c0);
            float sj = lo + hi;
            sj += __shfl_xor_sync(0xffffffffu, sj, 1);   // combine halves
            if (half == 0) svs[j][row] = sj;
            tmax = fmaxf(tmax, sj);
        }

        // rescale running state
        float corr = __expf(mi - tmax);
        li *= corr;
        {
            unsigned long long corr2;
            PACK2(corr2, corr, corr);
#pragma unroll
            for (int i = 0; i < 16; i++) F2MULI(o2[i], corr2);
        }
        __syncwarp();   // svs writes (even lanes) -> reads (all lanes)

        // ---- PV pass ----
#pragma unroll 8
        for (int j = 0; j < BN; j++) {
            float p = __expf(svs[j][row] - tmax);
            li += p;
            unsigned long long p2;
            PACK2(p2, p, p);
            const ulonglong2* vp = (const ulonglong2*)&Vss[j][half * 32];
#pragma unroll
            for (int dd = 0; dd < 8; dd++) {
                ulonglong2 vv = vp[dd];
                F2FMA(o2[2 * dd],     p2, vv.x);
                F2FMA(o2[2 * dd + 1], p2, vv.y);
            }
        }
        mi = tmax;
    }

    float inv = 1.f / li;
    const int b = bh >> 4;
    const int h = bh & 15;
    float* op = g_attn + ((size_t)(b * SEQ + r)) * EMBED + h * HDIM + half * 32;
#pragma unroll
    for (int i = 0; i < 8; i++) {
        float x0, x1, x2, x3;
        UNPACK2(x0, x1, o2[2 * i]);
        UNPACK2(x2, x3, o2[2 * i + 1]);
        float4 v;
        v.x = x0 * inv; v.y = x1 * inv; v.z = x2 * inv; v.w = x3 * inv;
        ((float4*)op)[i] = v;
    }
}

// ---------------------------------------------------------------------------
// GEMM 2: out = attn @ w_proj + b_proj (f32x2, PROVEN PASSING — R12 verbatim)
// ---------------------------------------------------------------------------
__global__ __launch_bounds__(256, 2)
void proj_gemm(const float* __restrict__ W,
               const float* __restrict__ bias,
               float* __restrict__ C)
{
    __shared__ float As[2][16][132];
    __shared__ float Bs[2][16][128];

    const int K = EMBED;
    const int NC = EMBED;
    const int tid = threadIdx.x;
    const int m0 = blockIdx.y * 128;
    const int n0 = blockIdx.x * 128;
    const int tx = tid & 15;
    const int ty = tid >> 4;

    const int arow0 = tid >> 2, ac4 = tid & 3;
    const int arow1 = arow0 + 64;
    const int brow0 = tid >> 5, bc4 = tid & 31;
    const int brow1 = brow0 + 8;

    unsigned long long acc2[8][4];
#pragma unroll
    for (int i = 0; i < 8; i++)
#pragma unroll
        for (int j = 0; j < 4; j++) acc2[i][j] = 0ULL;

    const float* A = g_attn;

    float4 ra0, ra1, rb0, rb1;
    ra0 = *(const float4*)&A[(size_t)(m0 + arow0) * K + ac4 * 4];
    ra1 = *(const float4*)&A[(size_t)(m0 + arow1) * K + ac4 * 4];
    rb0 = *(const float4*)&W[(size_t)brow0 * NC + n0 + bc4 * 4];
    rb1 = *(const float4*)&W[(size_t)brow1 * NC + n0 + bc4 * 4];

    for (int i = 0; i < K / 16; i++) {
        const int s = i & 1;

        As[s][ac4 * 4 + 0][arow0] = ra0.x;
        As[s][ac4 * 4 + 1][arow0] = ra0.y;
        As[s][ac4 * 4 + 2][arow0] = ra0.z;
        As[s][ac4 * 4 + 3][arow0] = ra0.w;
        As[s][ac4 * 4 + 0][arow1] = ra1.x;
        As[s][ac4 * 4 + 1][arow1] = ra1.y;
        As[s][ac4 * 4 + 2][arow1] = ra1.z;
        As[s][ac4 * 4 + 3][arow1] = ra1.w;
        *(float4*)&Bs[s][brow0][bc4 * 4] = rb0;
        *(float4*)&Bs[s][brow1][bc4 * 4] = rb1;

        if (i + 1 < K / 16) {
            int k0 = (i + 1) * 16;
            ra0 = *(const float4*)&A[(size_t)(m0 + arow0) * K + k0 + ac4 * 4];
            ra1 = *(const float4*)&A[(size_t)(m0 + arow1) * K + k0 + ac4 * 4];
            rb0 = *(const float4*)&W[(size_t)(k0 + brow0) * NC + n0 + bc4 * 4];
            rb1 = *(const float4*)&W[(size_t)(k0 + brow1) * NC + n0 + bc4 * 4];
        }

        __syncthreads();

#pragma unroll
        for (int kk = 0; kk < 16; kk++) {
            float a[8];
            *(float4*)&a[0] = *(const float4*)&As[s][kk][ty * 8];
            *(float4*)&a[4] = *(const float4*)&As[s][kk][ty * 8 + 4];
            ulonglong2 b01 = *(const ulonglong2*)&Bs[s][kk][tx * 8];
            ulonglong2 b23 = *(const ulonglong2*)&Bs[s][kk][tx * 8 + 4];
#pragma unroll
            for (int ii = 0; ii < 8; ii++) {
                unsigned long long a2;
                PACK2(a2, a[ii], a[ii]);
                F2FMA(acc2[ii][0], a2, b01.x);
                F2FMA(acc2[ii][1], a2, b01.y);
                F2FMA(acc2[ii][2], a2, b23.x);
                F2FMA(acc2[ii][3], a2, b23.y);
            }
        }
    }

#pragma unroll
    for (int i = 0; i < 8; i++) {
        int m = m0 + ty * 8 + i;
        int jc = n0 + tx * 8;
        float c0, c1, c2, c3, c4, c5, c6, c7;
        UNPACK2(c0, c1, acc2[i][0]);
        UNPACK2(c2, c3, acc2[i][1]);
        UNPACK2(c4, c5, acc2[i][2]);
        UNPACK2(c6, c7, acc2[i][3]);
        float4 v0, v1;
        v0.x = c0 + bias[jc + 0]; v0.y = c1 + bias[jc + 1];
        v0.z = c2 + bias[jc + 2]; v0.w = c3 + bias[jc + 3];
        v1.x = c4 + bias[jc + 4]; v1.y = c5 + bias[jc + 5];
        v1.z = c6 + bias[jc + 6]; v1.w = c7 + bias[jc + 7];
        *(float4*)&C[(size_t)m * NC + jc] = v0;
        *(float4*)&C[(size_t)m * NC + jc + 4] = v1;
    }
}

// ---------------------------------------------------------------------------
// kernel_launch: bare launches only.
// ---------------------------------------------------------------------------
extern "C" void kernel_launch(void* const* d_in, const int* in_sizes, int n_in,
                              void* d_out, int out_size)
{
    const float* x      = (const float*)d_in[0];
    const float* w_qkv  = (const float*)d_in[1];
    const float* b_qkv  = (const float*)d_in[2];
    const float* w_proj = (const float*)d_in[3];
    const float* b_proj = (const float*)d_in[4];
    float* out = (float*)d_out;

    dim3 g1(QKV_COLS / 128, MROWS / 128);   // (24, 32)
    qkv_gemm<<<g1, 256>>>(x, w_qkv, b_qkv);

    dim3 g2(SEQ / 64, BATCH * NHEADS);      // (32, 32)
    attn_half<<<g2, 128>>>();

    dim3 g3(EMBED / 128, MROWS / 128);      // (8, 32)
    proj_gemm<<<g3, 256>>>(w_proj, b_proj, out);
}

// round 17
// speedup vs baseline: 1.0017x; 1.0017x over previous
#include <cuda_runtime.h>
#include <math.h>

// Problem constants
#define EMBED 1024
#define NHEADS 16
#define HDIM 64
#define BATCH 2
#define SEQ 2048
#define MROWS (BATCH * SEQ)        // 4096
#define QKV_COLS (3 * EMBED)       // 3072
#define ATT_SCALE 0.125f           // 64^-0.5

// Scratch (allocation-free rule: __device__ globals)
__device__ float g_qkv[3 * BATCH * NHEADS * SEQ * HDIM];
__device__ float g_attn[BATCH * SEQ * EMBED];

// ---------------------------------------------------------------------------
// Packed f32x2 helpers (proven-passing path)
// ---------------------------------------------------------------------------
#define F2FMA(d, a, b) \
    asm("fma.rn.f32x2 %0, %1, %2, %0;" : "+l"(d) : "l"(a), "l"(b))
#define F2MUL(d, a, b) \
    asm("mul.rn.f32x2 %0, %1, %2;" : "=l"(d) : "l"(a), "l"(b))
#define F2MULI(d, b) \
    asm("mul.rn.f32x2 %0, %0, %1;" : "+l"(d) : "l"(b))
#define F2ADDI(d, b) \
    asm("add.rn.f32x2 %0, %0, %1;" : "+l"(d) : "l"(b))
#define PACK2(d, lo, hi) \
    asm("mov.b64 %0, {%1, %2};" : "=l"(d) : "f"(lo), "f"(hi))
#define UNPACK2(lo, hi, v) \
    asm("mov.b64 {%0, %1}, %2;" : "=f"(lo), "=f"(hi) : "l"(v))

// ---------------------------------------------------------------------------
// GEMM 1: qkv = x @ w_qkv + b_qkv (f32x2, PROVEN PASSING — unchanged from R12)
// ---------------------------------------------------------------------------
__global__ __launch_bounds__(256, 2)
void qkv_gemm(const float* __restrict__ A,
              const float* __restrict__ W,
              const float* __restrict__ bias)
{
    __shared__ float As[2][16][132];
    __shared__ float Bs[2][16][128];

    const int K = EMBED;
    const int NC = QKV_COLS;
    const int tid = threadIdx.x;
    const int m0 = blockIdx.y * 128;
    const int n0 = blockIdx.x * 128;
    const int tx = tid & 15;
    const int ty = tid >> 4;

    const int arow0 = tid >> 2, ac4 = tid & 3;
    const int arow1 = arow0 + 64;
    const int brow0 = tid >> 5, bc4 = tid & 31;
    const int brow1 = brow0 + 8;

    unsigned long long acc2[8][4];
#pragma unroll
    for (int i = 0; i < 8; i++)
#pragma unroll
        for (int j = 0; j < 4; j++) acc2[i][j] = 0ULL;

    float4 ra0, ra1, rb0, rb1;
    ra0 = *(const float4*)&A[(size_t)(m0 + arow0) * K + ac4 * 4];
    ra1 = *(const float4*)&A[(size_t)(m0 + arow1) * K + ac4 * 4];
    rb0 = *(const float4*)&W[(size_t)brow0 * NC + n0 + bc4 * 4];
    rb1 = *(const float4*)&W[(size_t)brow1 * NC + n0 + bc4 * 4];

    for (int i = 0; i < K / 16; i++) {
        const int s = i & 1;

        As[s][ac4 * 4 + 0][arow0] = ra0.x;
        As[s][ac4 * 4 + 1][arow0] = ra0.y;
        As[s][ac4 * 4 + 2][arow0] = ra0.z;
        As[s][ac4 * 4 + 3][arow0] = ra0.w;
        As[s][ac4 * 4 + 0][arow1] = ra1.x;
        As[s][ac4 * 4 + 1][arow1] = ra1.y;
        As[s][ac4 * 4 + 2][arow1] = ra1.z;
        As[s][ac4 * 4 + 3][arow1] = ra1.w;
        *(float4*)&Bs[s][brow0][bc4 * 4] = rb0;
        *(float4*)&Bs[s][brow1][bc4 * 4] = rb1;

        if (i + 1 < K / 16) {
            int k0 = (i + 1) * 16;
            ra0 = *(const float4*)&A[(size_t)(m0 + arow0) * K + k0 + ac4 * 4];
            ra1 = *(const float4*)&A[(size_t)(m0 + arow1) * K + k0 + ac4 * 4];
            rb0 = *(const float4*)&W[(size_t)(k0 + brow0) * NC + n0 + bc4 * 4];
            rb1 = *(const float4*)&W[(size_t)(k0 + brow1) * NC + n0 + bc4 * 4];
        }

        __syncthreads();

#pragma unroll
        for (int kk = 0; kk < 16; kk++) {
            float a[8];
            *(float4*)&a[0] = *(const float4*)&As[s][kk][ty * 8];
            *(float4*)&a[4] = *(const float4*)&As[s][kk][ty * 8 + 4];
            ulonglong2 b01 = *(const ulonglong2*)&Bs[s][kk][tx * 8];
            ulonglong2 b23 = *(const ulonglong2*)&Bs[s][kk][tx * 8 + 4];
#pragma unroll
            for (int ii = 0; ii < 8; ii++) {
                unsigned long long a2;
                PACK2(a2, a[ii], a[ii]);
                F2FMA(acc2[ii][0], a2, b01.x);
                F2FMA(acc2[ii][1], a2, b01.y);
                F2FMA(acc2[ii][2], a2, b23.x);
                F2FMA(acc2[ii][3], a2, b23.y);
            }
        }
    }

    {
        int jc0 = n0 + tx * 8;
        int sI = jc0 >> 10;
        int rem = jc0 & 1023;
        int h = rem >> 6;
        int d = rem & 63;
        float b0 = bias[jc0 + 0], b1 = bias[jc0 + 1], b2 = bias[jc0 + 2], b3 = bias[jc0 + 3];
        float b4 = bias[jc0 + 4], b5 = bias[jc0 + 5], b6 = bias[jc0 + 6], b7 = bias[jc0 + 7];
#pragma unroll
        for (int i = 0; i < 8; i++) {
            int m = m0 + ty * 8 + i;
            int b = m >> 11;
            int n = m & 2047;
            float c0, c1, c2, c3, c4, c5, c6, c7;
            UNPACK2(c0, c1, acc2[i][0]);
            UNPACK2(c2, c3, acc2[i][1]);
            UNPACK2(c4, c5, acc2[i][2]);
            UNPACK2(c6, c7, acc2[i][3]);
            float* dst = &g_qkv[(((size_t)((sI * BATCH + b) * NHEADS + h)) * SEQ + n) * HDIM + d];
            float4 v0, v1;
            v0.x = c0 + b0; v0.y = c1 + b1; v0.z = c2 + b2; v0.w = c3 + b3;
            v1.x = c4 + b4; v1.y = c5 + b5; v1.z = c6 + b6; v1.w = c7 + b7;
            *(float4*)dst = v0;
            *(float4*)(dst + 4) = v1;
        }
    }
}

// ---------------------------------------------------------------------------
// Flash attention v4: half-row per thread, 256 threads = 128 query rows/CTA
// (same K/V reuse as R12 baseline, half the per-thread registers ->
//  ~2 CTAs x 256 thr = 4 warps/SMSP for latency hiding).
// K/V tiles of 32 keys, single-buffered; scores staged in smem.
// ---------------------------------------------------------------------------
#define BN 32

__global__ __launch_bounds__(256)
void attn_half()
{
    __shared__ float Ks[BN][HDIM];
    __shared__ float Vss[BN][HDIM];
    __shared__ float svs[BN][128];

    const int tid = threadIdx.x;
    const int row = tid >> 1;              // local row 0..127
    const int half = tid & 1;              // dim half
    const int bh = blockIdx.y;             // 0..31
    const int r = blockIdx.x * 128 + row;  // global query row

    const float* Qp = g_qkv + ((size_t)bh * SEQ + r) * HDIM + half * 32;
    const float* Kb = g_qkv + ((size_t)(32 + bh) * SEQ) * HDIM;
    const float* Vb = g_qkv + ((size_t)(64 + bh) * SEQ) * HDIM;

    // q: own 32 dims = 16 u64, pre-scaled
    unsigned long long q2[16];
    {
        unsigned long long sc2;
        PACK2(sc2, ATT_SCALE, ATT_SCALE);
        const ulonglong2* Qp2 = (const ulonglong2*)Qp;
#pragma unroll
        for (int i = 0; i < 8; i++) {
            ulonglong2 tq = Qp2[i];
            F2MUL(q2[2 * i],     tq.x, sc2);
            F2MUL(q2[2 * i + 1], tq.y, sc2);
        }
    }

    unsigned long long o2[16];
#pragma unroll
    for (int i = 0; i < 16; i++) o2[i] = 0ULL;
    float mi = -INFINITY, li = 0.f;

    for (int t = 0; t < SEQ / BN; t++) {
        const int kb = t * BN;

        __syncthreads();   // prior tile's smem reads complete
        // load K,V tile: 32x64 each = 512 float4 per matrix; 2 each per thread
#pragma unroll
        for (int i = 0; i < 2; i++) {
            int idx = tid + i * 256;
            int kr = idx >> 4, c4 = idx & 15;
            *(float4*)&Ks[kr][c4 * 4]  = *(const float4*)&Kb[(size_t)(kb + kr) * HDIM + c4 * 4];
            *(float4*)&Vss[kr][c4 * 4] = *(const float4*)&Vb[(size_t)(kb + kr) * HDIM + c4 * 4];
        }
        __syncthreads();

        // ---- S pass: s_j = q . K_j (half-dot + shuffle combine) ----
        float tmax = mi;
#pragma unroll 8
        for (int j = 0; j < BN; j++) {
            unsigned long long c0 = 0ULL, c1 = 0ULL, c2 = 0ULL, c3 = 0ULL;
            const ulonglong2* kp = (const ulonglong2*)&Ks[j][half * 32];
#pragma unroll
            for (int dd = 0; dd < 4; dd++) {
                ulonglong2 k0 = kp[2 * dd];
                ulonglong2 k1 = kp[2 * dd + 1];
                F2FMA(c0, q2[4 * dd + 0], k0.x);
                F2FMA(c1, q2[4 * dd + 1], k0.y);
                F2FMA(c2, q2[4 * dd + 2], k1.x);
                F2FMA(c3, q2[4 * dd + 3], k1.y);
            }
            F2ADDI(c0, c2);
            F2ADDI(c1, c3);
            F2ADDI(c0, c1);
            float lo, hi;
            UNPACK2(lo, hi, c0);
            float sj = lo + hi;
            sj += __shfl_xor_sync(0xffffffffu, sj, 1);   // combine halves
            if (half == 0) svs[j][row] = sj;
            tmax = fmaxf(tmax, sj);
        }

        // rescale running state
        float corr = __expf(mi - tmax);
        li *= corr;
        {
            unsigned long long corr2;
            PACK2(corr2, corr, corr);
#pragma unroll
            for (int i = 0; i < 16; i++) F2MULI(o2[i], corr2);
        }
        __syncwarp();   // svs writes (even lanes) -> reads (same-warp lanes)

        // ---- PV pass ----
#pragma unroll 8
        for (int j = 0; j < BN; j++) {
            float p = __expf(svs[j][row] - tmax);
            li += p;
            unsigned long long p2;
            PACK2(p2, p, p);
            const ulonglong2* vp = (const ulonglong2*)&Vss[j][half * 32];
#pragma unroll
            for (int dd = 0; dd < 8; dd++) {
                ulonglong2 vv = vp[dd];
                F2FMA(o2[2 * dd],     p2, vv.x);
                F2FMA(o2[2 * dd + 1], p2, vv.y);
            }
        }
        mi = tmax;
    }

    float inv = 1.f / li;
    const int b = bh >> 4;
    const int h = bh & 15;
    float* op = g_attn + ((size_t)(b * SEQ + r)) * EMBED + h * HDIM + half * 32;
#pragma unroll
    for (int i = 0; i < 8; i++) {
        float x0, x1, x2, x3;
        UNPACK2(x0, x1, o2[2 * i]);
        UNPACK2(x2, x3, o2[2 * i + 1]);
        float4 v;
        v.x = x0 * inv; v.y = x1 * inv; v.z = x2 * inv; v.w = x3 * inv;
        ((float4*)op)[i] = v;
    }
}

// ---------------------------------------------------------------------------
// GEMM 2: out = attn @ w_proj + b_proj (f32x2, PROVEN PASSING — R12 verbatim)
// ---------------------------------------------------------------------------
__global__ __launch_bounds__(256, 2)
void proj_gemm(const float* __restrict__ W,
               const float* __restrict__ bias,
               float* __restrict__ C)
{
    __shared__ float As[2][16][132];
    __shared__ float Bs[2][16][128];

    const int K = EMBED;
    const int NC = EMBED;
    const int tid = threadIdx.x;
    const int m0 = blockIdx.y * 128;
    const int n0 = blockIdx.x * 128;
    const int tx = tid & 15;
    const int ty = tid >> 4;

    const int arow0 = tid >> 2, ac4 = tid & 3;
    const int arow1 = arow0 + 64;
    const int brow0 = tid >> 5, bc4 = tid & 31;
    const int brow1 = brow0 + 8;

    unsigned long long acc2[8][4];
#pragma unroll
    for (int i = 0; i < 8; i++)
#pragma unroll
        for (int j = 0; j < 4; j++) acc2[i][j] = 0ULL;

    const float* A = g_attn;

    float4 ra0, ra1, rb0, rb1;
    ra0 = *(const float4*)&A[(size_t)(m0 + arow0) * K + ac4 * 4];
    ra1 = *(const float4*)&A[(size_t)(m0 + arow1) * K + ac4 * 4];
    rb0 = *(const float4*)&W[(size_t)brow0 * NC + n0 + bc4 * 4];
    rb1 = *(const float4*)&W[(size_t)brow1 * NC + n0 + bc4 * 4];

    for (int i = 0; i < K / 16; i++) {
        const int s = i & 1;

        As[s][ac4 * 4 + 0][arow0] = ra0.x;
        As[s][ac4 * 4 + 1][arow0] = ra0.y;
        As[s][ac4 * 4 + 2][arow0] = ra0.z;
        As[s][ac4 * 4 + 3][arow0] = ra0.w;
        As[s][ac4 * 4 + 0][arow1] = ra1.x;
        As[s][ac4 * 4 + 1][arow1] = ra1.y;
        As[s][ac4 * 4 + 2][arow1] = ra1.z;
        As[s][ac4 * 4 + 3][arow1] = ra1.w;
        *(float4*)&Bs[s][brow0][bc4 * 4] = rb0;
        *(float4*)&Bs[s][brow1][bc4 * 4] = rb1;

        if (i + 1 < K / 16) {
            int k0 = (i + 1) * 16;
            ra0 = *(const float4*)&A[(size_t)(m0 + arow0) * K + k0 + ac4 * 4];
            ra1 = *(const float4*)&A[(size_t)(m0 + arow1) * K + k0 + ac4 * 4];
            rb0 = *(const float4*)&W[(size_t)(k0 + brow0) * NC + n0 + bc4 * 4];
            rb1 = *(const float4*)&W[(size_t)(k0 + brow1) * NC + n0 + bc4 * 4];
        }

        __syncthreads();

#pragma unroll
        for (int kk = 0; kk < 16; kk++) {
            float a[8];
            *(float4*)&a[0] = *(const float4*)&As[s][kk][ty * 8];
            *(float4*)&a[4] = *(const float4*)&As[s][kk][ty * 8 + 4];
            ulonglong2 b01 = *(const ulonglong2*)&Bs[s][kk][tx * 8];
            ulonglong2 b23 = *(const ulonglong2*)&Bs[s][kk][tx * 8 + 4];
#pragma unroll
            for (int ii = 0; ii < 8; ii++) {
                unsigned long long a2;
                PACK2(a2, a[ii], a[ii]);
                F2FMA(acc2[ii][0], a2, b01.x);
                F2FMA(acc2[ii][1], a2, b01.y);
                F2FMA(acc2[ii][2], a2, b23.x);
                F2FMA(acc2[ii][3], a2, b23.y);
            }
        }
    }

#pragma unroll
    for (int i = 0; i < 8; i++) {
        int m = m0 + ty * 8 + i;
        int jc = n0 + tx * 8;
        float c0, c1, c2, c3, c4, c5, c6, c7;
        UNPACK2(c0, c1, acc2[i][0]);
        UNPACK2(c2, c3, acc2[i][1]);
        UNPACK2(c4, c5, acc2[i][2]);
        UNPACK2(c6, c7, acc2[i][3]);
        float4 v0, v1;
        v0.x = c0 + bias[jc + 0]; v0.y = c1 + bias[jc + 1];
        v0.z = c2 + bias[jc + 2]; v0.w = c3 + bias[jc + 3];
        v1.x = c4 + bias[jc + 4]; v1.y = c5 + bias[jc + 5];
        v1.z = c6 + bias[jc + 6]; v1.w = c7 + bias[jc + 7];
        *(float4*)&C[(size_t)m * NC + jc] = v0;
        *(float4*)&C[(size_t)m * NC + jc + 4] = v1;
    }
}

// ---------------------------------------------------------------------------
// kernel_launch: bare launches only.
// ---------------------------------------------------------------------------
extern "C" void kernel_launch(void* const* d_in, const int* in_sizes, int n_in,
                              void* d_out, int out_size)
{
    const float* x      = (const float*)d_in[0];
    const float* w_qkv  = (const float*)d_in[1];
    const float* b_qkv  = (const float*)d_in[2];
    const float* w_proj = (const float*)d_in[3];
    const float* b_proj = (const float*)d_in[4];
    float* out = (float*)d_out;

    dim3 g1(QKV_COLS / 128, MROWS / 128);   // (24, 32)
    qkv_gemm<<<g1, 256>>>(x, w_qkv, b_qkv);

    dim3 g2(SEQ / 128, BATCH * NHEADS);     // (16, 32)
    attn_half<<<g2, 256>>>();

    dim3 g3(EMBED / 128, MROWS / 128);      // (8, 32)
    proj_gemm<<<g3, 256>>>(w_proj, b_proj, out);
}